// round 8
// baseline (speedup 1.0000x reference)
#include <cuda_runtime.h>
#include <math.h>

// ---------------------------------------------------------------------------
// Problem constants
// ---------------------------------------------------------------------------
#define BATCH   2
#define SEQ     2048
#define FDIM    1024
#define HIDD    1024
#define NHEAD   16
#define DHEAD   64
#define MLPD    4096
#define MROWS   (BATCH*SEQ)      // 4096 token rows

typedef unsigned long long u64t;

// packed f32x2 helpers (sm_100+)
#define FMA2(d, a, b) asm("fma.rn.f32x2 %0, %1, %2, %0;" : "+l"(d) : "l"(a), "l"(b))
#define MUL2(d, a, b) asm("mul.rn.f32x2 %0, %1, %2;" : "=l"(d) : "l"(a), "l"(b))

union F2U { u64t u; float2 f; };

__device__ __forceinline__ u64t pack_dup(float v) {
    F2U t; t.f = make_float2(v, v); return t.u;
}
__device__ __forceinline__ float2 unpack2(u64t u) {
    F2U t; t.u = u; return t.f;
}

// ---------------------------------------------------------------------------
// Scratch (static device allocations — no cudaMalloc allowed)
// ---------------------------------------------------------------------------
__device__ float g_h   [(size_t)MROWS*FDIM];
__device__ float g_q   [(size_t)MROWS*HIDD];
__device__ float g_k   [(size_t)MROWS*HIDD];
__device__ float g_v   [(size_t)MROWS*HIDD];
__device__ float g_attn[(size_t)MROWS*HIDD];
__device__ float g_res1[(size_t)MROWS*FDIM];
__device__ float g_h2  [(size_t)MROWS*FDIM];
__device__ float g_m1  [(size_t)MROWS*MLPD];

// ---------------------------------------------------------------------------
// LayerNorm: one block per row (F = 1024), 256 threads, float4
// ---------------------------------------------------------------------------
__global__ __launch_bounds__(256) void ln_kernel(
    const float* __restrict__ x, float* __restrict__ y,
    const float* __restrict__ g, const float* __restrict__ b)
{
    const int row  = blockIdx.x;
    const int tid  = threadIdx.x;
    const int lane = tid & 31;
    const int warp = tid >> 5;

    const float4* xr = (const float4*)(x + (size_t)row * FDIM);
    float4 v = xr[tid];

    float s = v.x + v.y + v.z + v.w;
    float q = v.x*v.x + v.y*v.y + v.z*v.z + v.w*v.w;
    #pragma unroll
    for (int off = 16; off; off >>= 1) {
        s += __shfl_xor_sync(0xffffffffu, s, off);
        q += __shfl_xor_sync(0xffffffffu, q, off);
    }
    __shared__ float ss[8], sq[8];
    if (lane == 0) { ss[warp] = s; sq[warp] = q; }
    __syncthreads();
    float ts = 0.f, tq = 0.f;
    #pragma unroll
    for (int i = 0; i < 8; i++) { ts += ss[i]; tq += sq[i]; }

    const float mu  = ts * (1.0f / FDIM);
    const float var = tq * (1.0f / FDIM) - mu * mu;
    const float rs  = rsqrtf(var + 1e-5f);

    float4 gg = ((const float4*)g)[tid];
    float4 bb = ((const float4*)b)[tid];
    float4 o;
    o.x = (v.x - mu) * rs * gg.x + bb.x;
    o.y = (v.y - mu) * rs * gg.y + bb.y;
    o.z = (v.z - mu) * rs * gg.z + bb.z;
    o.w = (v.w - mu) * rs * gg.w + bb.w;
    ((float4*)(y + (size_t)row * FDIM))[tid] = o;
}

// ---------------------------------------------------------------------------
// GEMM: C[M,N] = A[M,K] * B[N,K]^T  (+ fused epilogue), packed f32x2 math.
//   EPI 0: store
//   EPI 1: + bias + resid
//   EPI 2: gelu(+bias)
//   EPI 3: gelu(+bias) + resid
// 128x128 tile, BK=8, 256 threads, 8x8 microtile (acc = 8x4 packed pairs).
// A tile stored DUPLICATED in smem so LDS yields ready-packed (a,a) pairs.
// Double-buffered smem, one __syncthreads per K-step.
// ---------------------------------------------------------------------------
__device__ __forceinline__ float gelu_exact(float v)
{
    return 0.5f * v * (1.0f + erff(v * 0.70710678118654752f));
}

template<int EPI>
__global__ __launch_bounds__(256, 2) void gemm_tn(
    const float* __restrict__ A, const float* __restrict__ B, float* __restrict__ C,
    int M, int N, int K,
    const float* __restrict__ bias, const float* __restrict__ resid)
{
    __shared__ float As2[2][8][264];   // duplicated rows: 256 floats used (+8 pad)
    __shared__ float Bs [2][8][132];

    const int tid = threadIdx.x;
    const int bm  = blockIdx.y * 128;
    const int bn  = blockIdx.x * 128;

    // loaders: thread -> (row, k-quad)
    const int lr = tid >> 1;          // 0..127
    const int lk = (tid & 1) << 2;    // 0 or 4
    const float* Ald = A + (size_t)(bm + lr) * K + lk;
    const float* Bld = B + (size_t)(bn + lr) * K + lk;

    // compute mapping: 16x16 thread grid, 8x8 microtile
    const int tx = tid & 15;
    const int ty = tid >> 4;

    u64t acc[8][4];
    #pragma unroll
    for (int i = 0; i < 8; i++)
        #pragma unroll
        for (int j = 0; j < 4; j++) acc[i][j] = 0ull;

    // prologue: load tile 0, stage into buffer 0
    float4 a4 = *(const float4*)Ald;
    float4 b4 = *(const float4*)Bld;
    {
        *(float2*)&As2[0][lk+0][2*lr] = make_float2(a4.x, a4.x);
        *(float2*)&As2[0][lk+1][2*lr] = make_float2(a4.y, a4.y);
        *(float2*)&As2[0][lk+2][2*lr] = make_float2(a4.z, a4.z);
        *(float2*)&As2[0][lk+3][2*lr] = make_float2(a4.w, a4.w);
        Bs[0][lk+0][lr] = b4.x; Bs[0][lk+1][lr] = b4.y;
        Bs[0][lk+2][lr] = b4.z; Bs[0][lk+3][lr] = b4.w;
    }
    __syncthreads();

    int st = 0;
    for (int k0 = 0; k0 < K; k0 += 8) {
        const bool more = (k0 + 8 < K);
        if (more) {
            a4 = *(const float4*)(Ald + k0 + 8);
            b4 = *(const float4*)(Bld + k0 + 8);
        }

        #pragma unroll
        for (int kk = 0; kk < 8; kk++) {
            const ulonglong2* pa = (const ulonglong2*)&As2[st][kk][ty*16];
            const ulonglong2* pb = (const ulonglong2*)&Bs [st][kk][tx*8];
            u64t aa[8], bb[4];
            ulonglong2 t;
            t = pa[0]; aa[0] = t.x; aa[1] = t.y;
            t = pa[1]; aa[2] = t.x; aa[3] = t.y;
            t = pa[2]; aa[4] = t.x; aa[5] = t.y;
            t = pa[3]; aa[6] = t.x; aa[7] = t.y;
            t = pb[0]; bb[0] = t.x; bb[1] = t.y;
            t = pb[1]; bb[2] = t.x; bb[3] = t.y;
            #pragma unroll
            for (int i = 0; i < 8; i++) {
                FMA2(acc[i][0], aa[i], bb[0]);
                FMA2(acc[i][1], aa[i], bb[1]);
                FMA2(acc[i][2], aa[i], bb[2]);
                FMA2(acc[i][3], aa[i], bb[3]);
            }
        }

        if (more) {
            const int ns = st ^ 1;
            *(float2*)&As2[ns][lk+0][2*lr] = make_float2(a4.x, a4.x);
            *(float2*)&As2[ns][lk+1][2*lr] = make_float2(a4.y, a4.y);
            *(float2*)&As2[ns][lk+2][2*lr] = make_float2(a4.z, a4.z);
            *(float2*)&As2[ns][lk+3][2*lr] = make_float2(a4.w, a4.w);
            Bs[ns][lk+0][lr] = b4.x; Bs[ns][lk+1][lr] = b4.y;
            Bs[ns][lk+2][lr] = b4.z; Bs[ns][lk+3][lr] = b4.w;
            __syncthreads();
            st = ns;
        }
    }

    // fused epilogue, vectorized stores
    #pragma unroll
    for (int i = 0; i < 8; i++) {
        const size_t row = (size_t)(bm + ty*8 + i);
        #pragma unroll
        for (int jp = 0; jp < 4; jp += 2) {      // two packed pairs -> one float4
            const int col = bn + tx*8 + jp*2;
            float2 u0 = unpack2(acc[i][jp]);
            float2 u1 = unpack2(acc[i][jp+1]);
            float4 r; r.x = u0.x; r.y = u0.y; r.z = u1.x; r.w = u1.y;
            if (EPI >= 1) {
                float4 bb = *(const float4*)&bias[col];
                r.x += bb.x; r.y += bb.y; r.z += bb.z; r.w += bb.w;
            }
            if (EPI == 2 || EPI == 3) {
                r.x = gelu_exact(r.x); r.y = gelu_exact(r.y);
                r.z = gelu_exact(r.z); r.w = gelu_exact(r.w);
            }
            if (EPI == 1 || EPI == 3) {
                float4 rr = *(const float4*)&resid[row * (size_t)N + col];
                r.x += rr.x; r.y += rr.y; r.z += rr.z; r.w += rr.w;
            }
            *(float4*)&C[row * (size_t)N + col] = r;
        }
    }
}

// ---------------------------------------------------------------------------
// Flash attention (fp32, f32x2 math): dh=64, 64-query blocks, 64-key tiles.
// Grid: (SEQ/64, BATCH*NHEAD), 256 threads (8 warps x 8 query rows each).
// Lane owns ADJACENT column/dim pair (2*lane, 2*lane+1) so K/V pairs are
// single LDS.64; Q and P tiles are stored duplicated for packed broadcasts.
// scale = 1/sqrt(HID) = 1/32 folded into Q on load.
// ---------------------------------------------------------------------------
#define FA_QS2   (64*128)            // Qs duplicated [r][2d]
#define FA_KT    (64*66)             // Kt[d][c], stride 66 (even, 8B-aligned pairs)
#define FA_VS    (64*64)             // Vs[c][d]
#define FA_PS2   (64*128)            // Ps duplicated [r][2c]
#define FA_SMEM_FLOATS (FA_QS2 + FA_KT + FA_VS + FA_PS2)
#define FA_SMEM_BYTES  (FA_SMEM_FLOATS * 4)

__global__ __launch_bounds__(256) void flash_attn_kernel(
    const float* __restrict__ Q, const float* __restrict__ K,
    const float* __restrict__ V, float* __restrict__ O)
{
    extern __shared__ float sm[];
    float* Qs2 = sm;                   // [64][128]
    float* Kt  = Qs2 + FA_QS2;         // [64][66]  Kt[d*66+c]
    float* Vs  = Kt  + FA_KT;          // [64][64]  Vs[c*64+d]
    float* Ps2 = Vs  + FA_VS;          // [64][128]

    const int tid  = threadIdx.x;
    const int lane = tid & 31;
    const int warp = tid >> 5;
    const int b    = blockIdx.y >> 4;
    const int h    = blockIdx.y & 15;
    const size_t base = ((size_t)b * SEQ) * HIDD + (size_t)h * DHEAD;
    const int q0    = blockIdx.x * 64;
    const int rbase = warp * 8;

    // Load + scale Q tile (duplicated)
    #pragma unroll
    for (int j = 0; j < 4; j++) {
        int idx = tid + j * 256;                 // 1024 float4s
        int r  = idx >> 4;
        int dq = (idx & 15) << 2;
        float4 qv = *(const float4*)(Q + base + (size_t)(q0 + r) * HIDD + dq);
        qv.x *= 0.03125f; qv.y *= 0.03125f; qv.z *= 0.03125f; qv.w *= 0.03125f;
        *(float2*)&Qs2[r*128 + 2*(dq+0)] = make_float2(qv.x, qv.x);
        *(float2*)&Qs2[r*128 + 2*(dq+1)] = make_float2(qv.y, qv.y);
        *(float2*)&Qs2[r*128 + 2*(dq+2)] = make_float2(qv.z, qv.z);
        *(float2*)&Qs2[r*128 + 2*(dq+3)] = make_float2(qv.w, qv.w);
    }

    u64t  o2[8];
    float mi[8], li[8];
    #pragma unroll
    for (int r = 0; r < 8; r++) { o2[r] = 0ull; mi[r] = -1e30f; li[r] = 0.f; }

    for (int kt = 0; kt < SEQ; kt += 64) {
        __syncthreads();   // protect smem reuse (also makes Qs2 visible on iter 0)
        #pragma unroll
        for (int j = 0; j < 4; j++) {
            int idx = tid + j * 256;
            int c  = idx >> 4;
            int dq = (idx & 15) << 2;
            size_t g = base + (size_t)(kt + c) * HIDD + dq;
            float4 kv = *(const float4*)(K + g);
            Kt[(dq+0)*66 + c] = kv.x;
            Kt[(dq+1)*66 + c] = kv.y;
            Kt[(dq+2)*66 + c] = kv.z;
            Kt[(dq+3)*66 + c] = kv.w;
            float4 vv = *(const float4*)(V + g);
            *(float4*)&Vs[c*64 + dq] = vv;
        }
        __syncthreads();

        // S = Q*K^T ; lane owns key columns (2*lane, 2*lane+1) as one packed pair
        u64t s2[8];
        #pragma unroll
        for (int r = 0; r < 8; r++) s2[r] = 0ull;
        #pragma unroll
        for (int d4 = 0; d4 < 16; d4++) {
            const int dd = d4 << 2;
            const u64t k0p = *(const u64t*)&Kt[(dd+0)*66 + 2*lane];
            const u64t k1p = *(const u64t*)&Kt[(dd+1)*66 + 2*lane];
            const u64t k2p = *(const u64t*)&Kt[(dd+2)*66 + 2*lane];
            const u64t k3p = *(const u64t*)&Kt[(dd+3)*66 + 2*lane];
            #pragma unroll
            for (int r = 0; r < 8; r++) {
                const ulonglong2 qa = *(const ulonglong2*)&Qs2[(rbase + r)*128 + dd*2];
                const ulonglong2 qb = *(const ulonglong2*)&Qs2[(rbase + r)*128 + dd*2 + 4];
                FMA2(s2[r], qa.x, k0p);
                FMA2(s2[r], qa.y, k1p);
                FMA2(s2[r], qb.x, k2p);
                FMA2(s2[r], qb.y, k3p);
            }
        }

        // online softmax per row
        #pragma unroll
        for (int r = 0; r < 8; r++) {
            float2 sv = unpack2(s2[r]);
            float mx = fmaxf(sv.x, sv.y);
            #pragma unroll
            for (int off = 16; off; off >>= 1)
                mx = fmaxf(mx, __shfl_xor_sync(0xffffffffu, mx, off));
            const float mn    = fmaxf(mi[r], mx);
            const float alpha = __expf(mi[r] - mn);
            const float p0 = __expf(sv.x - mn);
            const float p1 = __expf(sv.y - mn);
            float ps = p0 + p1;
            #pragma unroll
            for (int off = 16; off; off >>= 1)
                ps += __shfl_xor_sync(0xffffffffu, ps, off);
            li[r] = li[r] * alpha + ps;
            const u64t ad = pack_dup(alpha);
            MUL2(o2[r], o2[r], ad);
            mi[r] = mn;
            float4 pp; pp.x = p0; pp.y = p0; pp.z = p1; pp.w = p1;
            *(float4*)&Ps2[(rbase + r)*128 + 4*lane] = pp;   // duplicated pairs
        }
        __syncwarp();

        // O += P * V ; lane owns output dims (2*lane, 2*lane+1)
        #pragma unroll
        for (int c4 = 0; c4 < 16; c4++) {
            const int cc = c4 << 2;
            const u64t v0p = *(const u64t*)&Vs[(cc+0)*64 + 2*lane];
            const u64t v1p = *(const u64t*)&Vs[(cc+1)*64 + 2*lane];
            const u64t v2p = *(const u64t*)&Vs[(cc+2)*64 + 2*lane];
            const u64t v3p = *(const u64t*)&Vs[(cc+3)*64 + 2*lane];
            #pragma unroll
            for (int r = 0; r < 8; r++) {
                const ulonglong2 pa = *(const ulonglong2*)&Ps2[(rbase + r)*128 + cc*2];
                const ulonglong2 pb = *(const ulonglong2*)&Ps2[(rbase + r)*128 + cc*2 + 4];
                FMA2(o2[r], pa.x, v0p);
                FMA2(o2[r], pa.y, v1p);
                FMA2(o2[r], pb.x, v2p);
                FMA2(o2[r], pb.y, v3p);
            }
        }
    }

    #pragma unroll
    for (int r = 0; r < 8; r++) {
        const float inv = 1.0f / li[r];
        float2 ov = unpack2(o2[r]);
        ov.x *= inv; ov.y *= inv;
        const size_t orow = base + (size_t)(q0 + rbase + r) * HIDD;
        *(float2*)&O[orow + 2*lane] = ov;
    }
}

// ---------------------------------------------------------------------------
// Launch
// ---------------------------------------------------------------------------
extern "C" void kernel_launch(void* const* d_in, const int* in_sizes, int n_in,
                              void* d_out, int out_size)
{
    const float* x     = (const float*)d_in[0];
    const float* la1_g = (const float*)d_in[1];
    const float* la1_b = (const float*)d_in[2];
    const float* Wq    = (const float*)d_in[3];
    const float* Wk    = (const float*)d_in[4];
    const float* Wv    = (const float*)d_in[5];
    const float* Wo    = (const float*)d_in[6];
    const float* bo    = (const float*)d_in[7];
    const float* la2_g = (const float*)d_in[8];
    const float* la2_b = (const float*)d_in[9];
    const float* W1    = (const float*)d_in[10];
    const float* b1    = (const float*)d_in[11];
    const float* W2    = (const float*)d_in[12];
    const float* b2    = (const float*)d_in[13];
    float* out = (float*)d_out;

    float *h, *q, *k, *v, *attn, *res1, *h2, *m1;
    cudaGetSymbolAddress((void**)&h,    g_h);
    cudaGetSymbolAddress((void**)&q,    g_q);
    cudaGetSymbolAddress((void**)&k,    g_k);
    cudaGetSymbolAddress((void**)&v,    g_v);
    cudaGetSymbolAddress((void**)&attn, g_attn);
    cudaGetSymbolAddress((void**)&res1, g_res1);
    cudaGetSymbolAddress((void**)&h2,   g_h2);
    cudaGetSymbolAddress((void**)&m1,   g_m1);

    cudaFuncSetAttribute(flash_attn_kernel,
                         cudaFuncAttributeMaxDynamicSharedMemorySize, FA_SMEM_BYTES);

    const dim3 blk(256);

    // 1) LN1: x -> h
    ln_kernel<<<MROWS, blk>>>(x, h, la1_g, la1_b);

    // 2) Q/K/V projections: h @ W^T
    {
        dim3 grid(HIDD/128, MROWS/128);
        gemm_tn<0><<<grid, blk>>>(h, Wq, q, MROWS, HIDD, FDIM, nullptr, nullptr);
        gemm_tn<0><<<grid, blk>>>(h, Wk, k, MROWS, HIDD, FDIM, nullptr, nullptr);
        gemm_tn<0><<<grid, blk>>>(h, Wv, v, MROWS, HIDD, FDIM, nullptr, nullptr);
    }

    // 3) attention (softmax(QK^T/32) V) -> attn  [B,N,HID]
    {
        dim3 grid(SEQ/64, BATCH*NHEAD);
        flash_attn_kernel<<<grid, blk, FA_SMEM_BYTES>>>(q, k, v, attn);
    }

    // 4) out = attn @ Wo^T + bo + x  -> res1
    {
        dim3 grid(FDIM/128, MROWS/128);
        gemm_tn<1><<<grid, blk>>>(attn, Wo, res1, MROWS, FDIM, HIDD, bo, x);
    }

    // 5) LN2: res1 -> h2
    ln_kernel<<<MROWS, blk>>>(res1, h2, la2_g, la2_b);

    // 6) m1 = gelu(h2 @ W1^T + b1)
    {
        dim3 grid(MLPD/128, MROWS/128);
        gemm_tn<2><<<grid, blk>>>(h2, W1, m1, MROWS, MLPD, FDIM, b1, nullptr);
    }

    // 7) out = gelu(m1 @ W2^T + b2) + res1
    {
        dim3 grid(FDIM/128, MROWS/128);
        gemm_tn<3><<<grid, blk>>>(m1, W2, out, MROWS, FDIM, MLPD, b2, res1);
    }
}